// round 5
// baseline (speedup 1.0000x reference)
#include <cuda_runtime.h>
#include <cuda_bf16.h>

// Problem constants
#define BB 4
#define NN 8192
#define KK 16
#define CC 128
#define TT 3
#define BN (BB*NN)          // 32768 rows total

#define NSM 152

// ---------------- device scratch ----------------
__device__ float g_feat[BN*CC];
__device__ float g_GP[BN*CC];     // gatherable part of edge layer-1 (incl. xyz term)
__device__ float g_bq[BN*CC];     // center part (incl. edge_b1)
__device__ float g_agg[BN*CC];
__device__ float g_h[BN*CC];      // update hidden
// transposed (k-major) weights
__device__ float g_offW1T[128*128];
__device__ float g_eW1fT[TT*128*128];
__device__ float g_eW2T[TT*128*128];
__device__ float g_uW1T[TT*256*128];
__device__ float g_uW2T[TT*128*128];

// ---------------- f32x2 helpers ----------------
__device__ __forceinline__ unsigned long long ffma2(unsigned long long a, unsigned long long b,
                                                    unsigned long long c) {
    unsigned long long d;
    asm("fma.rn.f32x2 %0, %1, %2, %3;" : "=l"(d) : "l"(a), "l"(b), "l"(c));
    return d;
}
__device__ __forceinline__ float f2lo(unsigned long long v){ return __uint_as_float((unsigned)v); }
__device__ __forceinline__ float f2hi(unsigned long long v){ return __uint_as_float((unsigned)(v>>32)); }
__device__ __forceinline__ unsigned long long bcast2(float f){
    unsigned long long r; unsigned u = __float_as_uint(f);
    asm("mov.b64 %0, {%1, %1};" : "=l"(r) : "r"(u));
    return r;
}

// col base for accumulator slot p (p=0,1 -> low 64 cols; p=2,3 -> high 64 cols)
__device__ __forceinline__ int colbase(int tx, int p) {
    return (p < 2) ? (tx*4 + p*2) : (64 + tx*4 + (p-2)*2);
}

// ---------------- shared GEMM core (software-pipelined) ----------------
// C[r][j] = sum_k sAT[k][r] * sBT[k][j]   (both tiles 128x128, k-major, stride 128)
// 256 threads: ty=tid>>4 (rows r=ty*8+u), tx=tid&15 (cols tx*4..+3 and 64+tx*4..+3)
// NOTE: prefetches one row past the tile (k=128); caller must guarantee 192
// readable floats beyond each tile (all tiles are followed by live smem + pad).
__device__ __forceinline__ void gemm128(const float* __restrict__ sAT,
                                        const float* __restrict__ sBT,
                                        unsigned long long acc[8][4],
                                        int ty, int tx)
{
    const float* aptr = sAT + ty*8;
    const float* bptr = sBT + tx*4;

    float4 a0c = *(const float4*)(aptr);
    float4 a1c = *(const float4*)(aptr + 4);
    ulonglong2 b0c = *(const ulonglong2*)(bptr);
    ulonglong2 b1c = *(const ulonglong2*)(bptr + 64);

    #pragma unroll 4
    for (int k = 0; k < 128; k++) {
        // prefetch k+1 while computing k
        float4 a0n = *(const float4*)(aptr + (k+1)*128);
        float4 a1n = *(const float4*)(aptr + (k+1)*128 + 4);
        ulonglong2 b0n = *(const ulonglong2*)(bptr + (k+1)*128);
        ulonglong2 b1n = *(const ulonglong2*)(bptr + (k+1)*128 + 64);

        float av[8] = {a0c.x,a0c.y,a0c.z,a0c.w,a1c.x,a1c.y,a1c.z,a1c.w};
        #pragma unroll
        for (int u = 0; u < 8; u++) {
            unsigned long long ap = bcast2(av[u]);
            acc[u][0] = ffma2(ap, b0c.x, acc[u][0]);
            acc[u][1] = ffma2(ap, b0c.y, acc[u][1]);
            acc[u][2] = ffma2(ap, b1c.x, acc[u][2]);
            acc[u][3] = ffma2(ap, b1c.y, acc[u][3]);
        }
        a0c = a0n; a1c = a1n; b0c = b0n; b1c = b1n;
    }
}

__device__ __forceinline__ void zero_acc(unsigned long long acc[8][4]) {
    #pragma unroll
    for (int u = 0; u < 8; u++)
        #pragma unroll
        for (int p = 0; p < 4; p++) acc[u][p] = 0ull;
}

// scatter-transpose a 128x128 row-major gmem tile into smem [k][r]
__device__ __forceinline__ void load_AT(const float* __restrict__ X,  // X = base + n0*128
                                        float* __restrict__ sAT, int tid)
{
    int r = tid & 127, half = tid >> 7;
    const float4* row = (const float4*)(X + (size_t)r*128) + half*16;
    #pragma unroll
    for (int c = 0; c < 16; c++) {
        float4 v = row[c];
        int i = half*64 + c*4;
        sAT[(i+0)*128 + r] = v.x;
        sAT[(i+1)*128 + r] = v.y;
        sAT[(i+2)*128 + r] = v.z;
        sAT[(i+3)*128 + r] = v.w;
    }
}

// copy a pre-transposed 128x128 weight tile gmem -> smem
__device__ __forceinline__ void load_W(const float* __restrict__ WT, float* __restrict__ sBT, int tid) {
    #pragma unroll
    for (int i = tid; i < 128*32; i += 256)
        ((float4*)sBT)[i] = ((const float4*)WT)[i];
}

// =======================================================================
// setup: transpose all weights into k-major scratch
// =======================================================================
__global__ void k_transpose(const float* __restrict__ offW1, const float* __restrict__ eW1,
                            const float* __restrict__ eW2,  const float* __restrict__ uW1,
                            const float* __restrict__ uW2)
{
    int tid = blockIdx.x*blockDim.x + threadIdx.x;  // 0..16383
    int k = tid >> 7, j = tid & 127;
    g_offW1T[tid] = offW1[j*128 + k];
    #pragma unroll
    for (int t = 0; t < TT; t++) {
        g_eW1fT[t*16384 + tid] = eW1[t*128*131 + j*131 + 3 + k];
        g_eW2T [t*16384 + tid] = eW2[t*16384 + j*128 + k];
        g_uW2T [t*16384 + tid] = uW2[t*16384 + j*128 + k];
        g_uW1T [t*32768 + tid]         = uW1[t*128*256 + j*256 + k];
        g_uW1T [t*32768 + 16384 + tid] = uW1[t*128*256 + j*256 + 128 + k];
    }
}

// =======================================================================
// Kernel A: offset MLP -> center -> bq  AND  GP, fused.  Tile = 128 nodes.
// =======================================================================
__global__ __launch_bounds__(256, 1)
void kA(const float* __restrict__ xyz,
        const float* __restrict__ offb1, const float* __restrict__ offW2,
        const float* __restrict__ offb2,
        const float* __restrict__ eW1, const float* __restrict__ eb1, int t)
{
    extern __shared__ float sm[];
    float* sFT    = sm;                 // 16384  feat^T [k][r]
    float* sW1    = sFT + 16384;        // 16384  offW1T (persistent)
    float* sWe    = sW1 + 16384;        // 16384  eW1fT  (persistent)
    float* sP     = sWe + 16384;        // 6144   delta partials [tx][r*3+d]
    float* sCen   = sP + 6144;          // 384    center [r*3+d]
    float* sXyz   = sCen + 384;         // 384    xyz tile [r*3+d]
    float* sW1x   = sXyz + 384;         // 384    eW1 xyz cols [d][j]
    float* sOffW2 = sW1x + 384;         // 384    [d][j]
    float* sB1    = sOffW2 + 384;       // 128
    float* sEB1   = sB1 + 128;          // 128
    float* sB2    = sEB1 + 128;         // 16 (+pad)

    const int tid = threadIdx.x;
    const int ty = tid >> 4, tx = tid & 15;

    load_W(g_offW1T, sW1, tid);
    load_W(g_eW1fT + t*16384, sWe, tid);
    for (int i = tid; i < 384; i += 256) {
        int d = i >> 7, j = i & 127;
        sW1x[i] = eW1[j*131 + d];
        sOffW2[i] = offW2[i];   // (3,128) row-major, same linear layout
    }
    if (tid < 128) { sB1[tid] = offb1[tid]; sEB1[tid] = eb1[tid]; }
    if (tid < 3) sB2[tid] = offb2[tid];
    __syncthreads();

    for (int tile = blockIdx.x; tile < BN/128; tile += gridDim.x) {
        const int n0 = tile * 128;
        load_AT(g_feat + (size_t)n0*128, sFT, tid);
        for (int i = tid; i < 384; i += 256) sXyz[i] = xyz[(size_t)n0*3 + i];
        __syncthreads();

        unsigned long long acc[8][4];
        zero_acc(acc);
        gemm128(sFT, sW1, acc, ty, tx);

        // h1 = relu(acc+b1); delta partials over this thread's 8 cols
        #pragma unroll
        for (int u = 0; u < 8; u++) {
            int r = ty*8 + u;
            float p0 = 0.f, p1 = 0.f, p2 = 0.f;
            #pragma unroll
            for (int p = 0; p < 4; p++) {
                int jb = colbase(tx, p);
                float lo = f2lo(acc[u][p]), hi = f2hi(acc[u][p]);
                float h0 = fmaxf(lo + sB1[jb], 0.f);
                float h1v = fmaxf(hi + sB1[jb+1], 0.f);
                p0 += h0*sOffW2[jb]     + h1v*sOffW2[jb+1];
                p1 += h0*sOffW2[128+jb] + h1v*sOffW2[128+jb+1];
                p2 += h0*sOffW2[256+jb] + h1v*sOffW2[256+jb+1];
            }
            sP[tx*384 + r*3 + 0] = p0;
            sP[tx*384 + r*3 + 1] = p1;
            sP[tx*384 + r*3 + 2] = p2;
        }
        __syncthreads();

        // reduce delta over tx, form center = xyz + delta + offb2
        if (tid < 192) {
            #pragma unroll
            for (int q = 0; q < 2; q++) {
                int o = tid*2 + q;  // 0..383 = r*3+d
                float s = 0.f;
                #pragma unroll
                for (int x = 0; x < 16; x++) s += sP[x*384 + o];
                int d = o - 3*(o/3);
                sCen[o] = s + sB2[d] + sXyz[o];
            }
        }
        __syncthreads();

        // GP GEMM (feature part), epilogue adds xyz part, writes GP and bq
        zero_acc(acc);
        gemm128(sFT, sWe, acc, ty, tx);

        #pragma unroll
        for (int u = 0; u < 8; u++) {
            int r = ty*8 + u;
            float x0 = sXyz[r*3], x1 = sXyz[r*3+1], x2 = sXyz[r*3+2];
            float c0 = sCen[r*3], c1 = sCen[r*3+1], c2 = sCen[r*3+2];
            #pragma unroll
            for (int p = 0; p < 4; p++) {
                int jb = colbase(tx, p);
                float lo = f2lo(acc[u][p]), hi = f2hi(acc[u][p]);
                float w0a = sW1x[jb],     w0b = sW1x[jb+1];
                float w1a = sW1x[128+jb], w1b = sW1x[128+jb+1];
                float w2a = sW1x[256+jb], w2b = sW1x[256+jb+1];
                float2 gp = make_float2(lo + x0*w0a + x1*w1a + x2*w2a,
                                        hi + x0*w0b + x1*w1b + x2*w2b);
                float2 bq = make_float2(sEB1[jb]   - (c0*w0a + c1*w1a + c2*w2a),
                                        sEB1[jb+1] - (c0*w0b + c1*w1b + c2*w2b));
                *(float2*)(g_GP + (size_t)(n0+r)*128 + jb) = gp;
                *(float2*)(g_bq + (size_t)(n0+r)*128 + jb) = bq;
            }
        }
        __syncthreads();
    }
}

// =======================================================================
// Kernel B: edge layer-2 + max over K.  Tile = 8 nodes (128 gathered rows).
// =======================================================================
__global__ __launch_bounds__(256, 1)
void kB(const int* __restrict__ knn, const float* __restrict__ eb2, int t)
{
    extern __shared__ float sm[];
    float* sHT  = sm;                // 16384  H^T [i][r] ; reused as C [r][j]
    float* sW   = sHT + 16384;       // 16384  eW2T (persistent)
    float* sBq  = sW + 16384;        // 1024   bq tile (8 nodes x 128)
    float* sB2  = sBq + 1024;        // 128
    int*   sIdx = (int*)(sB2 + 128); // 128 (+pad)

    const int tid = threadIdx.x;
    const int ty = tid >> 4, tx = tid & 15;

    load_W(g_eW2T + t*16384, sW, tid);
    if (tid < 128) sB2[tid] = eb2[tid];
    __syncthreads();

    for (int tile = blockIdx.x; tile < BN/8; tile += gridDim.x) {
        const int n0 = tile * 8;
        if (tid < 128) sIdx[tid] = knn[(size_t)n0*KK + tid];
        ((float4*)sBq)[tid] = ((const float4*)(g_bq + (size_t)n0*128))[tid];
        __syncthreads();

        // assemble H^T: row r = (node m=r/16, k=r%16); h = relu(GP[gid] + bq[m])
        {
            int r = tid & 127, half = tid >> 7;
            int m = r >> 4;
            int gn = n0 + m;
            int gid = ((gn >> 13) << 13) + sIdx[r];
            const float4* src = (const float4*)(g_GP + (size_t)gid*128) + half*16;
            const float4* bqr = (const float4*)(sBq + m*128) + half*16;
            #pragma unroll
            for (int c = 0; c < 16; c++) {
                float4 v = src[c], q = bqr[c];
                int i = half*64 + c*4;
                sHT[(i+0)*128 + r] = fmaxf(v.x + q.x, 0.f);
                sHT[(i+1)*128 + r] = fmaxf(v.y + q.y, 0.f);
                sHT[(i+2)*128 + r] = fmaxf(v.z + q.z, 0.f);
                sHT[(i+3)*128 + r] = fmaxf(v.w + q.w, 0.f);
            }
        }
        __syncthreads();

        unsigned long long acc[8][4];
        zero_acc(acc);
        gemm128(sHT, sW, acc, ty, tx);
        __syncthreads();  // all reads of sHT done -> reuse as C

        #pragma unroll
        for (int u = 0; u < 8; u++) {
            int r = ty*8 + u;
            #pragma unroll
            for (int p = 0; p < 4; p++) {
                int jb = colbase(tx, p);
                *(float2*)(sHT + r*128 + jb) = make_float2(f2lo(acc[u][p]), f2hi(acc[u][p]));
            }
        }
        __syncthreads();

        // max over 16 k per node + bias
        {
            int c = tid & 127, ug = tid >> 7;
            #pragma unroll
            for (int w = 0; w < 4; w++) {
                int m = ug*4 + w;
                float mx = -3.4e38f;
                #pragma unroll
                for (int k = 0; k < 16; k++)
                    mx = fmaxf(mx, sHT[(m*16 + k)*128 + c]);
                g_agg[(size_t)(n0+m)*128 + c] = mx + sB2[c];
            }
        }
        __syncthreads();
    }
}

// =======================================================================
// Kernel C1: update layer 1 (K=256 as two accumulating chunks) -> g_h
// =======================================================================
__global__ __launch_bounds__(256, 1)
void kC1(const float* __restrict__ ub1, int t)
{
    extern __shared__ float sm[];
    float* sAT = sm;            // 16384
    float* sW0 = sAT + 16384;   // 16384 uW1T chunk0 (persistent)
    float* sW1 = sW0 + 16384;   // 16384 uW1T chunk1 (persistent)
    float* sB1 = sW1 + 16384;   // 128 (+pad)

    const int tid = threadIdx.x;
    const int ty = tid >> 4, tx = tid & 15;

    load_W(g_uW1T + t*32768, sW0, tid);
    load_W(g_uW1T + t*32768 + 16384, sW1, tid);
    if (tid < 128) sB1[tid] = ub1[tid];
    __syncthreads();

    for (int tile = blockIdx.x; tile < BN/128; tile += gridDim.x) {
        const int n0 = tile * 128;
        unsigned long long acc[8][4];
        zero_acc(acc);

        load_AT(g_agg + (size_t)n0*128, sAT, tid);
        __syncthreads();
        gemm128(sAT, sW0, acc, ty, tx);
        __syncthreads();

        load_AT(g_feat + (size_t)n0*128, sAT, tid);
        __syncthreads();
        gemm128(sAT, sW1, acc, ty, tx);

        #pragma unroll
        for (int u = 0; u < 8; u++) {
            int r = ty*8 + u;
            #pragma unroll
            for (int p = 0; p < 4; p++) {
                int jb = colbase(tx, p);
                float2 h = make_float2(fmaxf(f2lo(acc[u][p]) + sB1[jb],   0.f),
                                       fmaxf(f2hi(acc[u][p]) + sB1[jb+1], 0.f));
                *(float2*)(g_h + (size_t)(n0+r)*128 + jb) = h;
            }
        }
        __syncthreads();
    }
}

// =======================================================================
// Kernel C2: update layer 2 + residual -> g_feat (and output on last iter)
// =======================================================================
__global__ __launch_bounds__(256, 1)
void kC2(const float* __restrict__ ub2, float* __restrict__ outp, int write_out, int t)
{
    extern __shared__ float sm[];
    float* sAT = sm;            // 16384
    float* sW  = sAT + 16384;   // 16384 uW2T (persistent)
    float* sB2 = sW + 16384;    // 128 (+pad)

    const int tid = threadIdx.x;
    const int ty = tid >> 4, tx = tid & 15;

    load_W(g_uW2T + t*16384, sW, tid);
    if (tid < 128) sB2[tid] = ub2[tid];
    __syncthreads();

    for (int tile = blockIdx.x; tile < BN/128; tile += gridDim.x) {
        const int n0 = tile * 128;
        load_AT(g_h + (size_t)n0*128, sAT, tid);
        __syncthreads();

        unsigned long long acc[8][4];
        zero_acc(acc);
        gemm128(sAT, sW, acc, ty, tx);

        #pragma unroll
        for (int u = 0; u < 8; u++) {
            int r = ty*8 + u;
            #pragma unroll
            for (int p = 0; p < 4; p++) {
                int jb = colbase(tx, p);
                float2 f = *(float2*)(g_feat + (size_t)(n0+r)*128 + jb);
                float2 v = make_float2(f.x + f2lo(acc[u][p]) + sB2[jb],
                                       f.y + f2hi(acc[u][p]) + sB2[jb+1]);
                *(float2*)(g_feat + (size_t)(n0+r)*128 + jb) = v;
                if (write_out) *(float2*)(outp + (size_t)(n0+r)*128 + jb) = v;
            }
        }
        __syncthreads();
    }
}

// =======================================================================
// launch
// =======================================================================
extern "C" void kernel_launch(void* const* d_in, const int* in_sizes, int n_in,
                              void* d_out, int out_size) {
    const float* xyz   = (const float*)d_in[0];
    const float* feat0 = (const float*)d_in[1];
    const int*   knn   = (const int*)d_in[2];
    const float* offW1 = (const float*)d_in[3];
    const float* offb1 = (const float*)d_in[4];
    const float* offW2 = (const float*)d_in[5];
    const float* offb2 = (const float*)d_in[6];
    const float* eW1   = (const float*)d_in[7];
    const float* eb1   = (const float*)d_in[8];
    const float* eW2   = (const float*)d_in[9];
    const float* eb2   = (const float*)d_in[10];
    const float* uW1   = (const float*)d_in[11];
    const float* ub1   = (const float*)d_in[12];
    const float* uW2   = (const float*)d_in[13];
    const float* ub2   = (const float*)d_in[14];
    float* outp = (float*)d_out;

    // +256 floats pad on every allocation: gemm128 prefetches one k-row (192
    // floats) past the end of its tiles; pad guarantees in-bounds smem reads.
    const size_t SMEM_A  = (size_t)(16384*3 + 6144 + 384*4 + 128*2 + 16 + 256) * 4;  // ~229.4 KB
    const size_t SMEM_B  = (size_t)(16384*2 + 1024 + 128 + 128 + 256) * 4;           // ~137.2 KB
    const size_t SMEM_C1 = (size_t)(16384*3 + 128 + 256) * 4;                        // ~198.1 KB
    const size_t SMEM_C2 = (size_t)(16384*2 + 128 + 256) * 4;                        // ~132.6 KB

    cudaFuncSetAttribute(kA,  cudaFuncAttributeMaxDynamicSharedMemorySize, (int)SMEM_A);
    cudaFuncSetAttribute(kB,  cudaFuncAttributeMaxDynamicSharedMemorySize, (int)SMEM_B);
    cudaFuncSetAttribute(kC1, cudaFuncAttributeMaxDynamicSharedMemorySize, (int)SMEM_C1);
    cudaFuncSetAttribute(kC2, cudaFuncAttributeMaxDynamicSharedMemorySize, (int)SMEM_C2);

    cudaMemcpyToSymbolAsync(g_feat, feat0, sizeof(float)*BN*CC, 0, cudaMemcpyDeviceToDevice, 0);
    k_transpose<<<64, 256>>>(offW1, eW1, eW2, uW1, uW2);

    for (int t = 0; t < TT; t++) {
        kA<<<NSM, 256, SMEM_A>>>(xyz, offb1, offW2, offb2,
                                 eW1 + (size_t)t*CC*(3+CC), eb1 + (size_t)t*CC, t);
        kB<<<NSM, 256, SMEM_B>>>(knn, eb2 + (size_t)t*CC, t);
        kC1<<<NSM, 256, SMEM_C1>>>(ub1 + (size_t)t*CC, t);
        kC2<<<NSM, 256, SMEM_C2>>>(ub2 + (size_t)t*CC, outp, (t == TT-1) ? 1 : 0, t);
    }
}

// round 8
// speedup vs baseline: 1.4657x; 1.4657x over previous
#include <cuda_runtime.h>
#include <cuda_bf16.h>
#include <cstdint>

// Problem constants
#define BB 4
#define NN 8192
#define KK 16
#define CC 128
#define TT 3
#define BN (BB*NN)          // 32768 rows total

#define NSM 152

// ---------------- device scratch ----------------
__device__ float g_feat[BN*CC];
__device__ float g_GP[BN*CC];     // gatherable part of edge layer-1 (incl. xyz term)
__device__ float g_bq[BN*CC];     // center part (incl. edge_b1)
__device__ float g_agg[BN*CC];
__device__ float g_h[BN*CC];      // update hidden
// transposed (k-major) weights for CUDA-core GEMMs
__device__ float g_offW1T[128*128];
__device__ float g_eW1fT[TT*128*128];
__device__ float g_uW1T[TT*256*128];
__device__ float g_uW2T[TT*128*128];
// bf16 hi/lo split of edge W2: [t][n][kpair] bf16x2 words ([N][K] row-major)
__device__ uint32_t g_Wbh16[TT*128*64];
__device__ uint32_t g_Wbl16[TT*128*64];

// ---------------- f32x2 helpers ----------------
__device__ __forceinline__ unsigned long long ffma2(unsigned long long a, unsigned long long b,
                                                    unsigned long long c) {
    unsigned long long d;
    asm("fma.rn.f32x2 %0, %1, %2, %3;" : "=l"(d) : "l"(a), "l"(b), "l"(c));
    return d;
}
__device__ __forceinline__ float f2lo(unsigned long long v){ return __uint_as_float((unsigned)v); }
__device__ __forceinline__ float f2hi(unsigned long long v){ return __uint_as_float((unsigned)(v>>32)); }
__device__ __forceinline__ unsigned long long bcast2(float f){
    unsigned long long r; unsigned u = __float_as_uint(f);
    asm("mov.b64 %0, {%1, %1};" : "=l"(r) : "r"(u));
    return r;
}
__device__ __forceinline__ int colbase(int tx, int p) {
    return (p < 2) ? (tx*4 + p*2) : (64 + tx*4 + (p-2)*2);
}

// ---------------- bf16 helpers ----------------
__device__ __forceinline__ uint32_t packbf(float lo, float hi){
    uint32_t r; asm("cvt.rn.bf16x2.f32 %0, %1, %2;" : "=r"(r) : "f"(hi), "f"(lo)); return r;
}
__device__ __forceinline__ float bflo(uint32_t u){ return __uint_as_float(u << 16); }
__device__ __forceinline__ float bfhi(uint32_t u){ return __uint_as_float(u & 0xffff0000u); }

__device__ __forceinline__ uint32_t smem_u32(const void* p) {
    uint32_t a;
    asm("{ .reg .u64 t; cvta.to.shared.u64 t, %1; cvt.u32.u64 %0, t; }" : "=r"(a) : "l"(p));
    return a;
}

// ---------------- mma.sync macros (base ISA, compiles for compute_103) ----------------
#define LDSM4(R, addr) \
    asm volatile("ldmatrix.sync.aligned.m8n8.x4.shared.b16 {%0,%1,%2,%3}, [%4];" \
        : "=r"((R)[0]), "=r"((R)[1]), "=r"((R)[2]), "=r"((R)[3]) : "r"(addr))

#define MMA16816(C, A, b0, b1) \
    asm volatile("mma.sync.aligned.m16n8k16.row.col.f32.bf16.bf16.f32 " \
        "{%0,%1,%2,%3}, {%4,%5,%6,%7}, {%8,%9}, {%0,%1,%2,%3};" \
        : "+f"((C)[0]), "+f"((C)[1]), "+f"((C)[2]), "+f"((C)[3]) \
        : "r"((A)[0]), "r"((A)[1]), "r"((A)[2]), "r"((A)[3]), "r"(b0), "r"(b1))

// ---------------- shared GEMM core (round-4, proven) ----------------
__device__ __forceinline__ void gemm128(const float* __restrict__ sAT,
                                        const float* __restrict__ sBT,
                                        unsigned long long acc[8][4],
                                        int ty, int tx)
{
    const float* aptr = sAT + ty*8;
    const float* bptr = sBT + tx*4;
    #pragma unroll 8
    for (int k = 0; k < 128; k++) {
        float4 a0 = *(const float4*)(aptr + k*128);
        float4 a1 = *(const float4*)(aptr + k*128 + 4);
        ulonglong2 b0 = *(const ulonglong2*)(bptr + k*128);
        ulonglong2 b1 = *(const ulonglong2*)(bptr + k*128 + 64);
        float av[8] = {a0.x,a0.y,a0.z,a0.w,a1.x,a1.y,a1.z,a1.w};
        #pragma unroll
        for (int u = 0; u < 8; u++) {
            unsigned long long ap = bcast2(av[u]);
            acc[u][0] = ffma2(ap, b0.x, acc[u][0]);
            acc[u][1] = ffma2(ap, b0.y, acc[u][1]);
            acc[u][2] = ffma2(ap, b1.x, acc[u][2]);
            acc[u][3] = ffma2(ap, b1.y, acc[u][3]);
        }
    }
}

__device__ __forceinline__ void zero_acc(unsigned long long acc[8][4]) {
    #pragma unroll
    for (int u = 0; u < 8; u++)
        #pragma unroll
        for (int p = 0; p < 4; p++) acc[u][p] = 0ull;
}

__device__ __forceinline__ void load_AT(const float* __restrict__ X,
                                        float* __restrict__ sAT, int tid)
{
    int r = tid & 127, half = tid >> 7;
    const float4* row = (const float4*)(X + (size_t)r*128) + half*16;
    #pragma unroll
    for (int c = 0; c < 16; c++) {
        float4 v = row[c];
        int i = half*64 + c*4;
        sAT[(i+0)*128 + r] = v.x;
        sAT[(i+1)*128 + r] = v.y;
        sAT[(i+2)*128 + r] = v.z;
        sAT[(i+3)*128 + r] = v.w;
    }
}

__device__ __forceinline__ void load_W(const float* __restrict__ WT, float* __restrict__ sBT, int tid) {
    #pragma unroll
    for (int i = tid; i < 128*32; i += 256)
        ((float4*)sBT)[i] = ((const float4*)WT)[i];
}

// =======================================================================
// setup kernels
// =======================================================================
__global__ void k_transpose(const float* __restrict__ offW1, const float* __restrict__ eW1,
                            const float* __restrict__ uW1,  const float* __restrict__ uW2)
{
    int tid = blockIdx.x*blockDim.x + threadIdx.x;  // 0..16383
    int k = tid >> 7, j = tid & 127;
    g_offW1T[tid] = offW1[j*128 + k];
    #pragma unroll
    for (int t = 0; t < TT; t++) {
        g_eW1fT[t*16384 + tid] = eW1[t*128*131 + j*131 + 3 + k];
        g_uW2T [t*16384 + tid] = uW2[t*16384 + j*128 + k];
        g_uW1T [t*32768 + tid]         = uW1[t*128*256 + j*256 + k];
        g_uW1T [t*32768 + 16384 + tid] = uW1[t*128*256 + j*256 + 128 + k];
    }
}

// bf16 hi/lo split of eW2 (plain [N][K] bf16x2 layout)
__global__ void k_prep_bf16(const float* __restrict__ eW2)
{
    int tid = blockIdx.x*blockDim.x + threadIdx.x;  // TT*128*64 = 24576
    if (tid >= TT*128*64) return;
    int p = tid & 63, n = (tid >> 6) & 127, t = tid >> 13;
    float w0 = eW2[t*16384 + n*128 + 2*p];
    float w1 = eW2[t*16384 + n*128 + 2*p + 1];
    uint32_t hi = packbf(w0, w1);
    uint32_t lo = packbf(w0 - bflo(hi), w1 - bfhi(hi));
    g_Wbh16[t*8192 + n*64 + p] = hi;
    g_Wbl16[t*8192 + n*64 + p] = lo;
}

// =======================================================================
// Kernel A: offset MLP -> center -> bq  AND  GP, fused.  Tile = 128 nodes.
// =======================================================================
__global__ __launch_bounds__(256, 1)
void kA(const float* __restrict__ xyz,
        const float* __restrict__ offb1, const float* __restrict__ offW2,
        const float* __restrict__ offb2,
        const float* __restrict__ eW1, const float* __restrict__ eb1, int t)
{
    extern __shared__ float sm[];
    float* sFT    = sm;                 // 16384
    float* sW1    = sFT + 16384;        // 16384
    float* sWe    = sW1 + 16384;        // 16384
    float* sP     = sWe + 16384;        // 6144
    float* sCen   = sP + 6144;          // 384
    float* sXyz   = sCen + 384;         // 384
    float* sW1x   = sXyz + 384;         // 384
    float* sOffW2 = sW1x + 384;         // 384
    float* sB1    = sOffW2 + 384;       // 128
    float* sEB1   = sB1 + 128;          // 128
    float* sB2    = sEB1 + 128;         // 16

    const int tid = threadIdx.x;
    const int ty = tid >> 4, tx = tid & 15;

    load_W(g_offW1T, sW1, tid);
    load_W(g_eW1fT + t*16384, sWe, tid);
    for (int i = tid; i < 384; i += 256) {
        int d = i >> 7, j = i & 127;
        sW1x[i] = eW1[j*131 + d];
        sOffW2[i] = offW2[i];
    }
    if (tid < 128) { sB1[tid] = offb1[tid]; sEB1[tid] = eb1[tid]; }
    if (tid < 3) sB2[tid] = offb2[tid];
    __syncthreads();

    for (int tile = blockIdx.x; tile < BN/128; tile += gridDim.x) {
        const int n0 = tile * 128;
        load_AT(g_feat + (size_t)n0*128, sFT, tid);
        for (int i = tid; i < 384; i += 256) sXyz[i] = xyz[(size_t)n0*3 + i];
        __syncthreads();

        unsigned long long acc[8][4];
        zero_acc(acc);
        gemm128(sFT, sW1, acc, ty, tx);

        #pragma unroll
        for (int u = 0; u < 8; u++) {
            int r = ty*8 + u;
            float p0 = 0.f, p1 = 0.f, p2 = 0.f;
            #pragma unroll
            for (int p = 0; p < 4; p++) {
                int jb = colbase(tx, p);
                float lo = f2lo(acc[u][p]), hi = f2hi(acc[u][p]);
                float h0 = fmaxf(lo + sB1[jb], 0.f);
                float h1v = fmaxf(hi + sB1[jb+1], 0.f);
                p0 += h0*sOffW2[jb]     + h1v*sOffW2[jb+1];
                p1 += h0*sOffW2[128+jb] + h1v*sOffW2[128+jb+1];
                p2 += h0*sOffW2[256+jb] + h1v*sOffW2[256+jb+1];
            }
            sP[tx*384 + r*3 + 0] = p0;
            sP[tx*384 + r*3 + 1] = p1;
            sP[tx*384 + r*3 + 2] = p2;
        }
        __syncthreads();

        if (tid < 192) {
            #pragma unroll
            for (int q = 0; q < 2; q++) {
                int o = tid*2 + q;
                float s = 0.f;
                #pragma unroll
                for (int x = 0; x < 16; x++) s += sP[x*384 + o];
                int d = o - 3*(o/3);
                sCen[o] = s + sB2[d] + sXyz[o];
            }
        }
        __syncthreads();

        zero_acc(acc);
        gemm128(sFT, sWe, acc, ty, tx);

        #pragma unroll
        for (int u = 0; u < 8; u++) {
            int r = ty*8 + u;
            float x0 = sXyz[r*3], x1 = sXyz[r*3+1], x2 = sXyz[r*3+2];
            float c0 = sCen[r*3], c1 = sCen[r*3+1], c2 = sCen[r*3+2];
            #pragma unroll
            for (int p = 0; p < 4; p++) {
                int jb = colbase(tx, p);
                float lo = f2lo(acc[u][p]), hi = f2hi(acc[u][p]);
                float w0a = sW1x[jb],     w0b = sW1x[jb+1];
                float w1a = sW1x[128+jb], w1b = sW1x[128+jb+1];
                float w2a = sW1x[256+jb], w2b = sW1x[256+jb+1];
                float2 gp = make_float2(lo + x0*w0a + x1*w1a + x2*w2a,
                                        hi + x0*w0b + x1*w1b + x2*w2b);
                float2 bq = make_float2(sEB1[jb]   - (c0*w0a + c1*w1a + c2*w2a),
                                        sEB1[jb+1] - (c0*w0b + c1*w1b + c2*w2b));
                *(float2*)(g_GP + (size_t)(n0+r)*128 + jb) = gp;
                *(float2*)(g_bq + (size_t)(n0+r)*128 + jb) = bq;
            }
        }
        __syncthreads();
    }
}

// =======================================================================
// Kernel Bm: edge layer-2 + max over K via mma.sync bf16 hi/lo split.
// Tile = 8 nodes (M=128 gathered rows) x N=128 x K=128.
// 8 warps: mb = wid&3 (rows mb*32..+31 = nodes 2mb,2mb+1), nb = wid>>2 (cols nb*64..+63)
// A/W smem rows padded to 136 bf16 (272 B) -> conflict-free ldmatrix.
// =======================================================================
#define BO_WHI 0
#define BO_WLO 34816
#define BO_AHI 69632
#define BO_ALO 104448
#define BO_B2  139264
#define SMEM_BM (139264 + 512)

__global__ __launch_bounds__(256, 1)
void kBm(const int* __restrict__ knn, const float* __restrict__ eb2, int t)
{
    extern __shared__ char smc[];
    const uint32_t sb = smem_u32(smc);
    float* sB2 = (float*)(smc + BO_B2);

    const int tid = threadIdx.x;
    const int wid = tid >> 5, l = tid & 31;
    const int mb = wid & 3, nb = wid >> 2;

    // load pre-split bf16 W into padded smem [n][136]
    {
        const uint2* wh = (const uint2*)(g_Wbh16 + t*8192);
        const uint2* wl = (const uint2*)(g_Wbl16 + t*8192);
        for (int i = tid; i < 4096; i += 256) {
            int n = i >> 5, p = i & 31;           // p = 8-byte unit (4 bf16)
            *(uint2*)(smc + BO_WHI + n*272 + p*8) = wh[i];
            *(uint2*)(smc + BO_WLO + n*272 + p*8) = wl[i];
        }
    }
    if (tid < 128) sB2[tid] = eb2[tid];
    __syncthreads();

    // per-thread ldmatrix smem base addresses (byte)
    const uint32_t aoff = (uint32_t)(mb*32*272 + (l & 15)*272 + ((l >> 4)*8)*2);
    const uint32_t boff = (uint32_t)(nb*64*272 + ((l & 7) + ((l >> 4) << 3))*272
                                     + (((l >> 3) & 1)*8)*2);
    const uint32_t aHi = sb + BO_AHI + aoff, aLo = sb + BO_ALO + aoff;
    const uint32_t bHi = sb + BO_WHI + boff, bLo = sb + BO_WLO + boff;

    // assembly indices
    const int r = tid & 127, half = tid >> 7;
    const int m = r >> 4;

    for (int tile = blockIdx.x; tile < BN/8; tile += gridDim.x) {
        const int n0 = tile * 8;

        // ---- assemble A = relu(GP[gather] + bq), bf16 hi/lo, rows [r][k] pad 136 ----
        {
            int gid = ((n0 >> 13) << 13) + knn[(size_t)n0*KK + r];
            const float4* src = (const float4*)(g_GP + (size_t)gid*128 + half*64);
            const float4* bqv = (const float4*)(g_bq + (size_t)(n0 + m)*128 + half*64);
            char* pH = smc + BO_AHI + r*272 + half*128;
            char* pL = smc + BO_ALO + r*272 + half*128;
            #pragma unroll
            for (int q = 0; q < 16; q++) {
                float4 v = src[q], w = bqv[q];
                float h0 = fmaxf(v.x + w.x, 0.f), h1 = fmaxf(v.y + w.y, 0.f);
                float h2 = fmaxf(v.z + w.z, 0.f), h3 = fmaxf(v.w + w.w, 0.f);
                uint32_t hA = packbf(h0, h1), hB = packbf(h2, h3);
                uint32_t lA = packbf(h0 - bflo(hA), h1 - bfhi(hA));
                uint32_t lB = packbf(h2 - bflo(hB), h3 - bfhi(hB));
                *(uint2*)(pH + q*8) = make_uint2(hA, hB);
                *(uint2*)(pL + q*8) = make_uint2(lA, lB);
            }
        }
        __syncthreads();

        // ---- MMA: D = Ahi*Whi + Ahi*Wlo + Alo*Whi ----
        float acc[2][8][4];
        #pragma unroll
        for (int a = 0; a < 2; a++)
            #pragma unroll
            for (int b = 0; b < 8; b++)
                #pragma unroll
                for (int c = 0; c < 4; c++) acc[a][b][c] = 0.f;

        #pragma unroll
        for (int ks = 0; ks < 8; ks++) {
            uint32_t ah[2][4], al[2][4], bh[4][4], bl[4][4];
            #pragma unroll
            for (int mt = 0; mt < 2; mt++) {
                LDSM4(ah[mt], aHi + mt*(16*272) + ks*32);
                LDSM4(al[mt], aLo + mt*(16*272) + ks*32);
            }
            #pragma unroll
            for (int np = 0; np < 4; np++) {
                LDSM4(bh[np], bHi + np*(16*272) + ks*32);
                LDSM4(bl[np], bLo + np*(16*272) + ks*32);
            }
            #pragma unroll
            for (int mt = 0; mt < 2; mt++)
                #pragma unroll
                for (int np = 0; np < 4; np++)
                    #pragma unroll
                    for (int sub = 0; sub < 2; sub++) {
                        int nt = np*2 + sub;
                        MMA16816(acc[mt][nt], ah[mt], bh[np][sub*2], bh[np][sub*2+1]);
                        MMA16816(acc[mt][nt], ah[mt], bl[np][sub*2], bl[np][sub*2+1]);
                        MMA16816(acc[mt][nt], al[mt], bh[np][sub*2], bh[np][sub*2+1]);
                    }
        }

        // ---- max over K (16 rows of each m16-tile = one node) + bias ----
        #pragma unroll
        for (int mt = 0; mt < 2; mt++) {
            int gn = n0 + mb*2 + mt;
            #pragma unroll
            for (int nt = 0; nt < 8; nt++) {
                float v0 = fmaxf(acc[mt][nt][0], acc[mt][nt][2]);
                float v1 = fmaxf(acc[mt][nt][1], acc[mt][nt][3]);
                #pragma unroll
                for (int o = 4; o <= 16; o <<= 1) {
                    v0 = fmaxf(v0, __shfl_xor_sync(0xffffffffu, v0, o));
                    v1 = fmaxf(v1, __shfl_xor_sync(0xffffffffu, v1, o));
                }
                if (l < 4) {
                    int col = nb*64 + nt*8 + l*2;
                    *(float2*)(g_agg + (size_t)gn*128 + col) =
                        make_float2(v0 + sB2[col], v1 + sB2[col+1]);
                }
            }
        }
        __syncthreads();
    }
}

// =======================================================================
// Kernel C1: update layer 1 (K=256 as two accumulating chunks) -> g_h
// =======================================================================
__global__ __launch_bounds__(256, 1)
void kC1(const float* __restrict__ ub1, int t)
{
    extern __shared__ float sm[];
    float* sAT = sm;            // 16384
    float* sW0 = sAT + 16384;   // 16384
    float* sW1 = sW0 + 16384;   // 16384
    float* sB1 = sW1 + 16384;   // 128

    const int tid = threadIdx.x;
    const int ty = tid >> 4, tx = tid & 15;

    load_W(g_uW1T + t*32768, sW0, tid);
    load_W(g_uW1T + t*32768 + 16384, sW1, tid);
    if (tid < 128) sB1[tid] = ub1[tid];
    __syncthreads();

    for (int tile = blockIdx.x; tile < BN/128; tile += gridDim.x) {
        const int n0 = tile * 128;
        unsigned long long acc[8][4];
        zero_acc(acc);

        load_AT(g_agg + (size_t)n0*128, sAT, tid);
        __syncthreads();
        gemm128(sAT, sW0, acc, ty, tx);
        __syncthreads();

        load_AT(g_feat + (size_t)n0*128, sAT, tid);
        __syncthreads();
        gemm128(sAT, sW1, acc, ty, tx);

        #pragma unroll
        for (int u = 0; u < 8; u++) {
            int r = ty*8 + u;
            #pragma unroll
            for (int p = 0; p < 4; p++) {
                int jb = colbase(tx, p);
                float2 h = make_float2(fmaxf(f2lo(acc[u][p]) + sB1[jb],   0.f),
                                       fmaxf(f2hi(acc[u][p]) + sB1[jb+1], 0.f));
                *(float2*)(g_h + (size_t)(n0+r)*128 + jb) = h;
            }
        }
        __syncthreads();
    }
}

// =======================================================================
// Kernel C2: update layer 2 + residual -> g_feat (and output on last iter)
// =======================================================================
__global__ __launch_bounds__(256, 1)
void kC2(const float* __restrict__ ub2, float* __restrict__ outp, int write_out, int t)
{
    extern __shared__ float sm[];
    float* sAT = sm;            // 16384
    float* sW  = sAT + 16384;   // 16384
    float* sB2 = sW + 16384;    // 128

    const int tid = threadIdx.x;
    const int ty = tid >> 4, tx = tid & 15;

    load_W(g_uW2T + t*16384, sW, tid);
    if (tid < 128) sB2[tid] = ub2[tid];
    __syncthreads();

    for (int tile = blockIdx.x; tile < BN/128; tile += gridDim.x) {
        const int n0 = tile * 128;
        load_AT(g_h + (size_t)n0*128, sAT, tid);
        __syncthreads();

        unsigned long long acc[8][4];
        zero_acc(acc);
        gemm128(sAT, sW, acc, ty, tx);

        #pragma unroll
        for (int u = 0; u < 8; u++) {
            int r = ty*8 + u;
            #pragma unroll
            for (int p = 0; p < 4; p++) {
                int jb = colbase(tx, p);
                float2 f = *(float2*)(g_feat + (size_t)(n0+r)*128 + jb);
                float2 v = make_float2(f.x + f2lo(acc[u][p]) + sB2[jb],
                                       f.y + f2hi(acc[u][p]) + sB2[jb+1]);
                *(float2*)(g_feat + (size_t)(n0+r)*128 + jb) = v;
                if (write_out) *(float2*)(outp + (size_t)(n0+r)*128 + jb) = v;
            }
        }
        __syncthreads();
    }
}

// =======================================================================
// launch
// =======================================================================
extern "C" void kernel_launch(void* const* d_in, const int* in_sizes, int n_in,
                              void* d_out, int out_size) {
    const float* xyz   = (const float*)d_in[0];
    const float* feat0 = (const float*)d_in[1];
    const int*   knn   = (const int*)d_in[2];
    const float* offW1 = (const float*)d_in[3];
    const float* offb1 = (const float*)d_in[4];
    const float* offW2 = (const float*)d_in[5];
    const float* offb2 = (const float*)d_in[6];
    const float* eW1   = (const float*)d_in[7];
    const float* eb1   = (const float*)d_in[8];
    const float* eW2   = (const float*)d_in[9];
    const float* eb2   = (const float*)d_in[10];
    const float* uW1   = (const float*)d_in[11];
    const float* ub1   = (const float*)d_in[12];
    const float* uW2   = (const float*)d_in[13];
    const float* ub2   = (const float*)d_in[14];
    float* outp = (float*)d_out;

    const size_t SMEM_A  = (size_t)(16384*3 + 6144 + 384*4 + 128*2 + 16 + 256) * 4;
    const size_t SMEM_C1 = (size_t)(16384*3 + 128 + 256) * 4;
    const size_t SMEM_C2 = (size_t)(16384*2 + 128 + 256) * 4;

    cudaFuncSetAttribute(kA,  cudaFuncAttributeMaxDynamicSharedMemorySize, (int)SMEM_A);
    cudaFuncSetAttribute(kBm, cudaFuncAttributeMaxDynamicSharedMemorySize, SMEM_BM);
    cudaFuncSetAttribute(kC1, cudaFuncAttributeMaxDynamicSharedMemorySize, (int)SMEM_C1);
    cudaFuncSetAttribute(kC2, cudaFuncAttributeMaxDynamicSharedMemorySize, (int)SMEM_C2);

    cudaMemcpyToSymbolAsync(g_feat, feat0, sizeof(float)*BN*CC, 0, cudaMemcpyDeviceToDevice, 0);
    k_transpose<<<64, 256>>>(offW1, eW1, uW1, uW2);
    k_prep_bf16<<<96, 256>>>(eW2);

    for (int t = 0; t < TT; t++) {
        kA<<<NSM, 256, SMEM_A>>>(xyz, offb1, offW2, offb2,
                                 eW1 + (size_t)t*CC*(3+CC), eb1 + (size_t)t*CC, t);
        kBm<<<NSM, 256, SMEM_BM>>>(knn, eb2 + (size_t)t*CC, t);
        kC1<<<NSM, 256, SMEM_C1>>>(ub1 + (size_t)t*CC, t);
        kC2<<<NSM, 256, SMEM_C2>>>(ub2 + (size_t)t*CC, outp, (t == TT-1) ? 1 : 0, t);
    }
}

// round 10
// speedup vs baseline: 1.8412x; 1.2562x over previous
#include <cuda_runtime.h>
#include <cuda_bf16.h>
#include <cstdint>

// Problem constants
#define BB 4
#define NN 8192
#define KK 16
#define CC 128
#define TT 3
#define BN (BB*NN)          // 32768 rows total

#define NSM 152
#define ROWPAD 272          // bytes per 128-k bf16 row (136 bf16) -> conflict-free ldmatrix
#define ATILE 34816         // 128*ROWPAD

// ---------------- device scratch ----------------
__device__ float g_feat[BN*CC];
__device__ float g_GP[BN*CC];     // gatherable part of edge layer-1 (incl. xyz term)
__device__ float g_bq[BN*CC];     // center part (incl. edge_b1)
__device__ float g_agg[BN*CC];
__device__ float g_h[BN*CC];      // update hidden
// bf16 hi/lo splits of all GEMM weights, [out][in] pairs (bf16x2 words)
__device__ uint32_t g_oW1h[128*64],      g_oW1l[128*64];       // offset W1
__device__ uint32_t g_eW1h[TT*128*64],   g_eW1l[TT*128*64];    // edge W1 feature cols
__device__ uint32_t g_eW2h[TT*128*64],   g_eW2l[TT*128*64];    // edge W2
__device__ uint32_t g_uW1h[TT*2*128*64], g_uW1l[TT*2*128*64];  // update W1 (2 k-chunks)
__device__ uint32_t g_uW2h[TT*128*64],   g_uW2l[TT*128*64];    // update W2

// ---------------- bf16 helpers ----------------
__device__ __forceinline__ uint32_t packbf(float lo, float hi){
    uint32_t r; asm("cvt.rn.bf16x2.f32 %0, %1, %2;" : "=r"(r) : "f"(hi), "f"(lo)); return r;
}
__device__ __forceinline__ float bflo(uint32_t u){ return __uint_as_float(u << 16); }
__device__ __forceinline__ float bfhi(uint32_t u){ return __uint_as_float(u & 0xffff0000u); }

__device__ __forceinline__ uint32_t smem_u32(const void* p) {
    uint32_t a;
    asm("{ .reg .u64 t; cvta.to.shared.u64 t, %1; cvt.u32.u64 %0, t; }" : "=r"(a) : "l"(p));
    return a;
}

// ---------------- mma.sync macros (base ISA) ----------------
#define LDSM4(R, addr) \
    asm volatile("ldmatrix.sync.aligned.m8n8.x4.shared.b16 {%0,%1,%2,%3}, [%4];" \
        : "=r"((R)[0]), "=r"((R)[1]), "=r"((R)[2]), "=r"((R)[3]) : "r"(addr))

#define MMA16816(C, A, b0, b1) \
    asm volatile("mma.sync.aligned.m16n8k16.row.col.f32.bf16.bf16.f32 " \
        "{%0,%1,%2,%3}, {%4,%5,%6,%7}, {%8,%9}, {%0,%1,%2,%3};" \
        : "+f"((C)[0]), "+f"((C)[1]), "+f"((C)[2]), "+f"((C)[3]) \
        : "r"((A)[0]), "r"((A)[1]), "r"((A)[2]), "r"((A)[3]), "r"(b0), "r"(b1))

__device__ __forceinline__ void zacc(float acc[2][8][4]) {
    #pragma unroll
    for (int a = 0; a < 2; a++)
        #pragma unroll
        for (int b = 0; b < 8; b++)
            #pragma unroll
            for (int c = 0; c < 4; c++) acc[a][b][c] = 0.f;
}

// 128x128x128 hi/lo-split MMA block: acc += A*B^T with 3-term compensation
__device__ __forceinline__ void mma_block(uint32_t aHi, uint32_t aLo,
                                          uint32_t bHi, uint32_t bLo,
                                          float acc[2][8][4])
{
    #pragma unroll
    for (int ks = 0; ks < 8; ks++) {
        uint32_t ah[2][4], al[2][4], bh[4][4], bl[4][4];
        #pragma unroll
        for (int mt = 0; mt < 2; mt++) {
            LDSM4(ah[mt], aHi + mt*(16*ROWPAD) + ks*32);
            LDSM4(al[mt], aLo + mt*(16*ROWPAD) + ks*32);
        }
        #pragma unroll
        for (int np = 0; np < 4; np++) {
            LDSM4(bh[np], bHi + np*(16*ROWPAD) + ks*32);
            LDSM4(bl[np], bLo + np*(16*ROWPAD) + ks*32);
        }
        #pragma unroll
        for (int mt = 0; mt < 2; mt++)
            #pragma unroll
            for (int np = 0; np < 4; np++)
                #pragma unroll
                for (int sub = 0; sub < 2; sub++) {
                    int nt = np*2 + sub;
                    MMA16816(acc[mt][nt], ah[mt], bh[np][sub*2], bh[np][sub*2+1]);
                    MMA16816(acc[mt][nt], ah[mt], bl[np][sub*2], bl[np][sub*2+1]);
                    MMA16816(acc[mt][nt], al[mt], bh[np][sub*2], bh[np][sub*2+1]);
                }
    }
}

// assemble A tile: rows [r][k] fp32 gmem -> smem bf16 hi/lo, ROWPAD rows
__device__ __forceinline__ void asm_A_rows(const float* __restrict__ X,
                                           char* aHiB, char* aLoB, int tid)
{
    int r = tid & 127, half = tid >> 7;
    const float4* src = (const float4*)(X + (size_t)r*128 + half*64);
    char* pH = aHiB + r*ROWPAD + half*128;
    char* pL = aLoB + r*ROWPAD + half*128;
    #pragma unroll
    for (int q = 0; q < 16; q++) {
        float4 v = src[q];
        uint32_t hA = packbf(v.x, v.y), hB = packbf(v.z, v.w);
        uint32_t lA = packbf(v.x - bflo(hA), v.y - bfhi(hA));
        uint32_t lB = packbf(v.z - bflo(hB), v.w - bfhi(hB));
        *(uint2*)(pH + q*8) = make_uint2(hA, hB);
        *(uint2*)(pL + q*8) = make_uint2(lA, lB);
    }
}

// copy pre-split weight (128x64 uint32 pairs) into padded smem rows
__device__ __forceinline__ void load_Wbf(const uint32_t* __restrict__ Wh,
                                         const uint32_t* __restrict__ Wl,
                                         char* wHiB, char* wLoB, int tid)
{
    const uint2* wh = (const uint2*)Wh;
    const uint2* wl = (const uint2*)Wl;
    #pragma unroll
    for (int i = tid; i < 4096; i += 256) {
        int n = i >> 5, p = i & 31;
        *(uint2*)(wHiB + n*ROWPAD + p*8) = wh[i];
        *(uint2*)(wLoB + n*ROWPAD + p*8) = wl[i];
    }
}

// =======================================================================
// setup: bf16 hi/lo split of all weights ([out][in] layout kept)
// =======================================================================
__device__ __forceinline__ void splitw(float w0, float w1, uint32_t* H, uint32_t* L, int idx) {
    uint32_t hi = packbf(w0, w1);
    uint32_t lo = packbf(w0 - bflo(hi), w1 - bfhi(hi));
    H[idx] = hi; L[idx] = lo;
}

__global__ void k_prep(const float* __restrict__ offW1, const float* __restrict__ eW1,
                       const float* __restrict__ eW2,  const float* __restrict__ uW1,
                       const float* __restrict__ uW2)
{
    int tid = blockIdx.x*blockDim.x + threadIdx.x;
    if (tid >= 128*64) return;
    int p = tid & 63, n = tid >> 6;
    splitw(offW1[n*128 + 2*p], offW1[n*128 + 2*p + 1], g_oW1h, g_oW1l, tid);
    #pragma unroll
    for (int t = 0; t < TT; t++) {
        splitw(eW1[t*128*131 + n*131 + 3 + 2*p], eW1[t*128*131 + n*131 + 3 + 2*p + 1],
               g_eW1h, g_eW1l, t*8192 + tid);
        splitw(eW2[t*16384 + n*128 + 2*p], eW2[t*16384 + n*128 + 2*p + 1],
               g_eW2h, g_eW2l, t*8192 + tid);
        splitw(uW2[t*16384 + n*128 + 2*p], uW2[t*16384 + n*128 + 2*p + 1],
               g_uW2h, g_uW2l, t*8192 + tid);
        #pragma unroll
        for (int kb = 0; kb < 2; kb++)
            splitw(uW1[t*32768 + n*256 + kb*128 + 2*p], uW1[t*32768 + n*256 + kb*128 + 2*p + 1],
                   g_uW1h, g_uW1l, t*16384 + kb*8192 + tid);
    }
}

// =======================================================================
// Kernel A (mma): offset MLP -> center -> bq AND GP.  Tile = 128 nodes.
// =======================================================================
#define AO_AH  0
#define AO_AL  34816
#define AO_W1H 69632
#define AO_W1L 104448
#define AO_WEH 139264
#define AO_WEL 174080
#define AO_F   208896
#define SMEM_KA (208896 + 2576*4)   // 219200

__global__ __launch_bounds__(256, 1)
void kA(const float* __restrict__ xyz, const float* __restrict__ feat0, int first,
        const float* __restrict__ offb1, const float* __restrict__ offW2,
        const float* __restrict__ offb2,
        const float* __restrict__ eW1, const float* __restrict__ eb1, int t)
{
    extern __shared__ char smc[];
    const uint32_t sb = smem_u32(smc);
    float* sF     = (float*)(smc + AO_F);
    float* sXyz   = sF;          // 384
    float* sCen   = sF + 384;    // 384
    float* sPd    = sF + 768;    // 768
    float* sW1x   = sF + 1536;   // 384
    float* sOffW2 = sF + 1920;   // 384
    float* sB1    = sF + 2304;   // 128
    float* sEB1   = sF + 2432;   // 128
    float* sB2    = sF + 2560;   // 16

    const int tid = threadIdx.x, wid = tid >> 5, l = tid & 31;
    const int mb = wid & 3, nb = wid >> 2;
    const float* fs = first ? feat0 : g_feat;

    load_Wbf(g_oW1h, g_oW1l, smc + AO_W1H, smc + AO_W1L, tid);
    load_Wbf(g_eW1h + t*8192, g_eW1l + t*8192, smc + AO_WEH, smc + AO_WEL, tid);
    for (int i = tid; i < 384; i += 256) {
        int d = i >> 7, j = i & 127;
        sW1x[i] = eW1[j*131 + d];
        sOffW2[i] = offW2[i];
    }
    if (tid < 128) { sB1[tid] = offb1[tid]; sEB1[tid] = eb1[tid]; }
    if (tid < 3) sB2[tid] = offb2[tid];

    const uint32_t aoff = (uint32_t)(mb*32*ROWPAD + (l & 15)*ROWPAD + ((l >> 4)*8)*2);
    const uint32_t boff = (uint32_t)(nb*64*ROWPAD + ((l & 7) + ((l >> 4) << 3))*ROWPAD
                                     + (((l >> 3) & 1)*8)*2);
    const uint32_t aHi = sb + AO_AH + aoff,  aLo = sb + AO_AL + aoff;
    const uint32_t w1H = sb + AO_W1H + boff, w1L = sb + AO_W1L + boff;
    const uint32_t weH = sb + AO_WEH + boff, weL = sb + AO_WEL + boff;
    __syncthreads();

    for (int tile = blockIdx.x; tile < BN/128; tile += gridDim.x) {
        const int n0 = tile * 128;
        asm_A_rows(fs + (size_t)n0*128, smc + AO_AH, smc + AO_AL, tid);
        for (int i = tid; i < 384; i += 256) sXyz[i] = xyz[(size_t)n0*3 + i];
        __syncthreads();

        float acc[2][8][4];
        zacc(acc);
        mma_block(aHi, aLo, w1H, w1L, acc);

        // delta partials: h1 = relu(C + b1); pr[mt][rowhalf][d] over this thread's cols
        float pr[2][2][3];
        #pragma unroll
        for (int a = 0; a < 2; a++)
            #pragma unroll
            for (int b = 0; b < 2; b++)
                #pragma unroll
                for (int d = 0; d < 3; d++) pr[a][b][d] = 0.f;
        #pragma unroll
        for (int mt = 0; mt < 2; mt++)
            #pragma unroll
            for (int nt = 0; nt < 8; nt++) {
                int c = nb*64 + nt*8 + (l & 3)*2;
                float h00 = fmaxf(acc[mt][nt][0] + sB1[c],   0.f);
                float h01 = fmaxf(acc[mt][nt][1] + sB1[c+1], 0.f);
                float h10 = fmaxf(acc[mt][nt][2] + sB1[c],   0.f);
                float h11 = fmaxf(acc[mt][nt][3] + sB1[c+1], 0.f);
                #pragma unroll
                for (int d = 0; d < 3; d++) {
                    float wa = sOffW2[d*128 + c], wb = sOffW2[d*128 + c + 1];
                    pr[mt][0][d] += h00*wa + h01*wb;
                    pr[mt][1][d] += h10*wa + h11*wb;
                }
            }
        #pragma unroll
        for (int mt = 0; mt < 2; mt++)
            #pragma unroll
            for (int rh = 0; rh < 2; rh++)
                #pragma unroll
                for (int d = 0; d < 3; d++) {
                    float v = pr[mt][rh][d];
                    v += __shfl_xor_sync(0xffffffffu, v, 1);
                    v += __shfl_xor_sync(0xffffffffu, v, 2);
                    pr[mt][rh][d] = v;
                }
        if ((l & 3) == 0) {
            #pragma unroll
            for (int mt = 0; mt < 2; mt++) {
                int r0 = mb*32 + mt*16 + (l >> 2);
                #pragma unroll
                for (int d = 0; d < 3; d++) {
                    sPd[nb*384 + r0*3 + d]       = pr[mt][0][d];
                    sPd[nb*384 + (r0+8)*3 + d]   = pr[mt][1][d];
                }
            }
        }
        __syncthreads();

        for (int o = tid; o < 384; o += 256) {
            int d = o - 3*(o/3);
            sCen[o] = sPd[o] + sPd[384 + o] + sB2[d] + sXyz[o];
        }
        __syncthreads();

        // GP GEMM (A unchanged in smem)
        zacc(acc);
        mma_block(aHi, aLo, weH, weL, acc);

        #pragma unroll
        for (int mt = 0; mt < 2; mt++) {
            #pragma unroll
            for (int rh = 0; rh < 2; rh++) {
                int r = mb*32 + mt*16 + (l >> 2) + rh*8;
                float x0 = sXyz[r*3], x1 = sXyz[r*3+1], x2 = sXyz[r*3+2];
                float c0 = sCen[r*3], c1 = sCen[r*3+1], c2 = sCen[r*3+2];
                #pragma unroll
                for (int nt = 0; nt < 8; nt++) {
                    int c = nb*64 + nt*8 + (l & 3)*2;
                    float aL = acc[mt][nt][rh*2], aH = acc[mt][nt][rh*2+1];
                    float w0a = sW1x[c],       w0b = sW1x[c+1];
                    float w1a = sW1x[128 + c], w1b = sW1x[128 + c + 1];
                    float w2a = sW1x[256 + c], w2b = sW1x[256 + c + 1];
                    *(float2*)(g_GP + (size_t)(n0+r)*128 + c) =
                        make_float2(aL + x0*w0a + x1*w1a + x2*w2a,
                                    aH + x0*w0b + x1*w1b + x2*w2b);
                    *(float2*)(g_bq + (size_t)(n0+r)*128 + c) =
                        make_float2(sEB1[c]   - (c0*w0a + c1*w1a + c2*w2a),
                                    sEB1[c+1] - (c0*w0b + c1*w1b + c2*w2b));
                }
            }
        }
        __syncthreads();
    }
}

// =======================================================================
// Kernel Bm: edge layer-2 + max over K (unchanged from round 8)
// =======================================================================
#define BO_WHI 0
#define BO_WLO 34816
#define BO_AHI 69632
#define BO_ALO 104448
#define BO_B2  139264
#define SMEM_BM (139264 + 512)

__global__ __launch_bounds__(256, 1)
void kBm(const int* __restrict__ knn, const float* __restrict__ eb2, int t)
{
    extern __shared__ char smc[];
    const uint32_t sb = smem_u32(smc);
    float* sB2 = (float*)(smc + BO_B2);

    const int tid = threadIdx.x;
    const int wid = tid >> 5, l = tid & 31;
    const int mb = wid & 3, nb = wid >> 2;

    load_Wbf(g_eW2h + t*8192, g_eW2l + t*8192, smc + BO_WHI, smc + BO_WLO, tid);
    if (tid < 128) sB2[tid] = eb2[tid];
    __syncthreads();

    const uint32_t aoff = (uint32_t)(mb*32*ROWPAD + (l & 15)*ROWPAD + ((l >> 4)*8)*2);
    const uint32_t boff = (uint32_t)(nb*64*ROWPAD + ((l & 7) + ((l >> 4) << 3))*ROWPAD
                                     + (((l >> 3) & 1)*8)*2);
    const uint32_t aHi = sb + BO_AHI + aoff, aLo = sb + BO_ALO + aoff;
    const uint32_t bHi = sb + BO_WHI + boff, bLo = sb + BO_WLO + boff;

    const int r = tid & 127, half = tid >> 7;
    const int m = r >> 4;

    for (int tile = blockIdx.x; tile < BN/8; tile += gridDim.x) {
        const int n0 = tile * 8;

        // assemble A = relu(GP[gather] + bq), bf16 hi/lo
        {
            int gid = ((n0 >> 13) << 13) + knn[(size_t)n0*KK + r];
            const float4* src = (const float4*)(g_GP + (size_t)gid*128 + half*64);
            const float4* bqv = (const float4*)(g_bq + (size_t)(n0 + m)*128 + half*64);
            char* pH = smc + BO_AHI + r*ROWPAD + half*128;
            char* pL = smc + BO_ALO + r*ROWPAD + half*128;
            #pragma unroll
            for (int q = 0; q < 16; q++) {
                float4 v = src[q], w = bqv[q];
                float h0 = fmaxf(v.x + w.x, 0.f), h1 = fmaxf(v.y + w.y, 0.f);
                float h2 = fmaxf(v.z + w.z, 0.f), h3 = fmaxf(v.w + w.w, 0.f);
                uint32_t hA = packbf(h0, h1), hB = packbf(h2, h3);
                uint32_t lA = packbf(h0 - bflo(hA), h1 - bfhi(hA));
                uint32_t lB = packbf(h2 - bflo(hB), h3 - bfhi(hB));
                *(uint2*)(pH + q*8) = make_uint2(hA, hB);
                *(uint2*)(pL + q*8) = make_uint2(lA, lB);
            }
        }
        __syncthreads();

        float acc[2][8][4];
        zacc(acc);
        mma_block(aHi, aLo, bHi, bLo, acc);

        // max over K (16 rows of each m16-tile = one node) + bias
        #pragma unroll
        for (int mt = 0; mt < 2; mt++) {
            int gn = n0 + mb*2 + mt;
            #pragma unroll
            for (int nt = 0; nt < 8; nt++) {
                float v0 = fmaxf(acc[mt][nt][0], acc[mt][nt][2]);
                float v1 = fmaxf(acc[mt][nt][1], acc[mt][nt][3]);
                #pragma unroll
                for (int o = 4; o <= 16; o <<= 1) {
                    v0 = fmaxf(v0, __shfl_xor_sync(0xffffffffu, v0, o));
                    v1 = fmaxf(v1, __shfl_xor_sync(0xffffffffu, v1, o));
                }
                if (l < 4) {
                    int col = nb*64 + nt*8 + l*2;
                    *(float2*)(g_agg + (size_t)gn*128 + col) =
                        make_float2(v0 + sB2[col], v1 + sB2[col+1]);
                }
            }
        }
        __syncthreads();
    }
}

// =======================================================================
// Kernel C1 (mma): update layer 1, K=256 as two chunks -> g_h
// =======================================================================
#define CO_AH  0
#define CO_AL  34816
#define CO_W0H 69632
#define CO_W0L 104448
#define CO_W1H 139264
#define CO_W1L 174080
#define CO_B1  208896
#define SMEM_KC1 (208896 + 512)

__global__ __launch_bounds__(256, 1)
void kC1(const float* __restrict__ feat0, int first, const float* __restrict__ ub1, int t)
{
    extern __shared__ char smc[];
    const uint32_t sb = smem_u32(smc);
    float* sB1 = (float*)(smc + CO_B1);

    const int tid = threadIdx.x, wid = tid >> 5, l = tid & 31;
    const int mb = wid & 3, nb = wid >> 2;
    const float* fs = first ? feat0 : g_feat;

    load_Wbf(g_uW1h + t*16384,        g_uW1l + t*16384,        smc + CO_W0H, smc + CO_W0L, tid);
    load_Wbf(g_uW1h + t*16384 + 8192, g_uW1l + t*16384 + 8192, smc + CO_W1H, smc + CO_W1L, tid);
    if (tid < 128) sB1[tid] = ub1[tid];

    const uint32_t aoff = (uint32_t)(mb*32*ROWPAD + (l & 15)*ROWPAD + ((l >> 4)*8)*2);
    const uint32_t boff = (uint32_t)(nb*64*ROWPAD + ((l & 7) + ((l >> 4) << 3))*ROWPAD
                                     + (((l >> 3) & 1)*8)*2);
    const uint32_t aHi = sb + CO_AH + aoff,  aLo = sb + CO_AL + aoff;
    const uint32_t w0H = sb + CO_W0H + boff, w0L = sb + CO_W0L + boff;
    const uint32_t w1H = sb + CO_W1H + boff, w1L = sb + CO_W1L + boff;
    __syncthreads();

    for (int tile = blockIdx.x; tile < BN/128; tile += gridDim.x) {
        const int n0 = tile * 128;
        float acc[2][8][4];
        zacc(acc);

        asm_A_rows(g_agg + (size_t)n0*128, smc + CO_AH, smc + CO_AL, tid);
        __syncthreads();
        mma_block(aHi, aLo, w0H, w0L, acc);
        __syncthreads();

        asm_A_rows(fs + (size_t)n0*128, smc + CO_AH, smc + CO_AL, tid);
        __syncthreads();
        mma_block(aHi, aLo, w1H, w1L, acc);

        #pragma unroll
        for (int mt = 0; mt < 2; mt++) {
            int r0 = mb*32 + mt*16 + (l >> 2);
            #pragma unroll
            for (int nt = 0; nt < 8; nt++) {
                int c = nb*64 + nt*8 + (l & 3)*2;
                *(float2*)(g_h + (size_t)(n0+r0)*128 + c) =
                    make_float2(fmaxf(acc[mt][nt][0] + sB1[c],   0.f),
                                fmaxf(acc[mt][nt][1] + sB1[c+1], 0.f));
                *(float2*)(g_h + (size_t)(n0+r0+8)*128 + c) =
                    make_float2(fmaxf(acc[mt][nt][2] + sB1[c],   0.f),
                                fmaxf(acc[mt][nt][3] + sB1[c+1], 0.f));
            }
        }
        __syncthreads();
    }
}

// =======================================================================
// Kernel C2 (mma): update layer 2 + residual -> g_feat (+ out on last iter)
// =======================================================================
#define DO_AH 0
#define DO_AL 34816
#define DO_WH 69632
#define DO_WL 104448
#define DO_B2 139264
#define SMEM_KC2 (139264 + 512)

__global__ __launch_bounds__(256, 1)
void kC2(const float* __restrict__ feat0, int first, const float* __restrict__ ub2,
         float* __restrict__ outp, int write_out, int t)
{
    extern __shared__ char smc[];
    const uint32_t sb = smem_u32(smc);
    float* sB2 = (float*)(smc + DO_B2);

    const int tid = threadIdx.x, wid = tid >> 5, l = tid & 31;
    const int mb = wid & 3, nb = wid >> 2;
    const float* fs = first ? feat0 : g_feat;

    load_Wbf(g_uW2h + t*8192, g_uW2l + t*8192, smc + DO_WH, smc + DO_WL, tid);
    if (tid < 128) sB2[tid] = ub2[tid];

    const uint32_t aoff = (uint32_t)(mb*32*ROWPAD + (l & 15)*ROWPAD + ((l >> 4)*8)*2);
    const uint32_t boff = (uint32_t)(nb*64*ROWPAD + ((l & 7) + ((l >> 4) << 3))*ROWPAD
                                     + (((l >> 3) & 1)*8)*2);
    const uint32_t aHi = sb + DO_AH + aoff, aLo = sb + DO_AL + aoff;
    const uint32_t wH  = sb + DO_WH + boff, wL  = sb + DO_WL + boff;
    __syncthreads();

    for (int tile = blockIdx.x; tile < BN/128; tile += gridDim.x) {
        const int n0 = tile * 128;
        asm_A_rows(g_h + (size_t)n0*128, smc + DO_AH, smc + DO_AL, tid);
        __syncthreads();

        float acc[2][8][4];
        zacc(acc);
        mma_block(aHi, aLo, wH, wL, acc);

        #pragma unroll
        for (int mt = 0; mt < 2; mt++) {
            #pragma unroll
            for (int rh = 0; rh < 2; rh++) {
                int r = mb*32 + mt*16 + (l >> 2) + rh*8;
                #pragma unroll
                for (int nt = 0; nt < 8; nt++) {
                    int c = nb*64 + nt*8 + (l & 3)*2;
                    float2 f = *(const float2*)(fs + (size_t)(n0+r)*128 + c);
                    float2 v = make_float2(f.x + acc[mt][nt][rh*2]   + sB2[c],
                                           f.y + acc[mt][nt][rh*2+1] + sB2[c+1]);
                    *(float2*)(g_feat + (size_t)(n0+r)*128 + c) = v;
                    if (write_out) *(float2*)(outp + (size_t)(n0+r)*128 + c) = v;
                }
            }
        }
        __syncthreads();
    }
}

// =======================================================================
// launch
// =======================================================================
extern "C" void kernel_launch(void* const* d_in, const int* in_sizes, int n_in,
                              void* d_out, int out_size) {
    const float* xyz   = (const float*)d_in[0];
    const float* feat0 = (const float*)d_in[1];
    const int*   knn   = (const int*)d_in[2];
    const float* offW1 = (const float*)d_in[3];
    const float* offb1 = (const float*)d_in[4];
    const float* offW2 = (const float*)d_in[5];
    const float* offb2 = (const float*)d_in[6];
    const float* eW1   = (const float*)d_in[7];
    const float* eb1   = (const float*)d_in[8];
    const float* eW2   = (const float*)d_in[9];
    const float* eb2   = (const float*)d_in[10];
    const float* uW1   = (const float*)d_in[11];
    const float* ub1   = (const float*)d_in[12];
    const float* uW2   = (const float*)d_in[13];
    const float* ub2   = (const float*)d_in[14];
    float* outp = (float*)d_out;

    cudaFuncSetAttribute(kA,  cudaFuncAttributeMaxDynamicSharedMemorySize, SMEM_KA);
    cudaFuncSetAttribute(kBm, cudaFuncAttributeMaxDynamicSharedMemorySize, SMEM_BM);
    cudaFuncSetAttribute(kC1, cudaFuncAttributeMaxDynamicSharedMemorySize, SMEM_KC1);
    cudaFuncSetAttribute(kC2, cudaFuncAttributeMaxDynamicSharedMemorySize, SMEM_KC2);

    k_prep<<<32, 256>>>(offW1, eW1, eW2, uW1, uW2);

    for (int t = 0; t < TT; t++) {
        int first = (t == 0) ? 1 : 0;
        kA<<<NSM, 256, SMEM_KA>>>(xyz, feat0, first, offb1, offW2, offb2,
                                  eW1 + (size_t)t*CC*(3+CC), eb1 + (size_t)t*CC, t);
        kBm<<<NSM, 256, SMEM_BM>>>(knn, eb2 + (size_t)t*CC, t);
        kC1<<<NSM, 256, SMEM_KC1>>>(feat0, first, ub1 + (size_t)t*CC, t);
        kC2<<<NSM, 256, SMEM_KC2>>>(feat0, first, ub2 + (size_t)t*CC, outp,
                                    (t == TT-1) ? 1 : 0, t);
    }
}

// round 17
// speedup vs baseline: 1.9295x; 1.0479x over previous
#include <cuda_runtime.h>
#include <cuda_bf16.h>
#include <cstdint>

// Problem constants
#define BB 4
#define NN 8192
#define KK 16
#define CC 128
#define TT 3
#define BN (BB*NN)          // 32768 rows total

#define NSM 152
#define NTH 512
#define ROWPAD 272          // bytes per 128-k bf16 row (136 bf16) -> conflict-free ldmatrix

// ---------------- device scratch ----------------
__device__ float g_feat[BN*CC];
__device__ float g_GP[BN*CC];     // gatherable part of edge layer-1 (incl. xyz term)
__device__ float g_bq[BN*CC];     // center part (incl. edge_b1)
__device__ float g_agg[BN*CC];
// bf16 hi/lo splits of all GEMM weights, [out][in] pairs (bf16x2 words)
__device__ uint32_t g_oW1h[128*64],      g_oW1l[128*64];       // offset W1
__device__ uint32_t g_eW1h[TT*128*64],   g_eW1l[TT*128*64];    // edge W1 feature cols
__device__ uint32_t g_eW2h[TT*128*64],   g_eW2l[TT*128*64];    // edge W2
__device__ uint32_t g_uW1h[TT*2*128*64], g_uW1l[TT*2*128*64];  // update W1 (2 k-chunks)
__device__ uint32_t g_uW2h[TT*128*64],   g_uW2l[TT*128*64];    // update W2

// ---------------- bf16 helpers ----------------
__device__ __forceinline__ uint32_t packbf(float lo, float hi){
    uint32_t r; asm("cvt.rn.bf16x2.f32 %0, %1, %2;" : "=r"(r) : "f"(hi), "f"(lo)); return r;
}
__device__ __forceinline__ float bflo(uint32_t u){ return __uint_as_float(u << 16); }
__device__ __forceinline__ float bfhi(uint32_t u){ return __uint_as_float(u & 0xffff0000u); }

__device__ __forceinline__ uint32_t smem_u32(const void* p) {
    uint32_t a;
    asm("{ .reg .u64 t; cvta.to.shared.u64 t, %1; cvt.u32.u64 %0, t; }" : "=r"(a) : "l"(p));
    return a;
}

// ---------------- mma.sync macros (base ISA) ----------------
#define LDSM4(R, addr) \
    asm volatile("ldmatrix.sync.aligned.m8n8.x4.shared.b16 {%0,%1,%2,%3}, [%4];" \
        : "=r"((R)[0]), "=r"((R)[1]), "=r"((R)[2]), "=r"((R)[3]) : "r"(addr))

#define MMA16816(C, A, b0, b1) \
    asm volatile("mma.sync.aligned.m16n8k16.row.col.f32.bf16.bf16.f32 " \
        "{%0,%1,%2,%3}, {%4,%5,%6,%7}, {%8,%9}, {%0,%1,%2,%3};" \
        : "+f"((C)[0]), "+f"((C)[1]), "+f"((C)[2]), "+f"((C)[3]) \
        : "r"((A)[0]), "r"((A)[1]), "r"((A)[2]), "r"((A)[3]), "r"(b0), "r"(b1))

__device__ __forceinline__ void zacc4(float acc[2][4][4]) {
    #pragma unroll
    for (int a = 0; a < 2; a++)
        #pragma unroll
        for (int b = 0; b < 4; b++)
            #pragma unroll
            for (int c = 0; c < 4; c++) acc[a][b][c] = 0.f;
}

// 128x(32-col)x128 hi/lo-split MMA: 16 warps, each warp mb (32 rows) x nb (32 cols)
__device__ __forceinline__ void mma_block4(uint32_t aHi, uint32_t aLo,
                                           uint32_t bHi, uint32_t bLo,
                                           float acc[2][4][4])
{
    #pragma unroll
    for (int ks = 0; ks < 8; ks++) {
        uint32_t ah[2][4], al[2][4], bh[2][4], bl[2][4];
        #pragma unroll
        for (int mt = 0; mt < 2; mt++) {
            LDSM4(ah[mt], aHi + mt*(16*ROWPAD) + ks*32);
            LDSM4(al[mt], aLo + mt*(16*ROWPAD) + ks*32);
        }
        #pragma unroll
        for (int np = 0; np < 2; np++) {
            LDSM4(bh[np], bHi + np*(16*ROWPAD) + ks*32);
            LDSM4(bl[np], bLo + np*(16*ROWPAD) + ks*32);
        }
        #pragma unroll
        for (int mt = 0; mt < 2; mt++)
            #pragma unroll
            for (int np = 0; np < 2; np++)
                #pragma unroll
                for (int sub = 0; sub < 2; sub++) {
                    int nt = np*2 + sub;
                    MMA16816(acc[mt][nt], ah[mt], bh[np][sub*2], bh[np][sub*2+1]);
                    MMA16816(acc[mt][nt], ah[mt], bl[np][sub*2], bl[np][sub*2+1]);
                    MMA16816(acc[mt][nt], al[mt], bh[np][sub*2], bh[np][sub*2+1]);
                }
    }
}

// assemble A tile (128x128 fp32 row-major gmem) -> smem bf16 hi/lo; 512 threads
__device__ __forceinline__ void asm_rows512(const float* __restrict__ X,
                                            char* aHiB, char* aLoB, int tid)
{
    int r = tid & 127, q4 = tid >> 7;     // q4 = quarter of the row
    const float4* src = (const float4*)(X + (size_t)r*128 + q4*32);
    char* pH = aHiB + r*ROWPAD + q4*64;
    char* pL = aLoB + r*ROWPAD + q4*64;
    #pragma unroll
    for (int q = 0; q < 8; q++) {
        float4 v = src[q];
        uint32_t hA = packbf(v.x, v.y), hB = packbf(v.z, v.w);
        uint32_t lA = packbf(v.x - bflo(hA), v.y - bfhi(hA));
        uint32_t lB = packbf(v.z - bflo(hB), v.w - bfhi(hB));
        *(uint2*)(pH + q*8) = make_uint2(hA, hB);
        *(uint2*)(pL + q*8) = make_uint2(lA, lB);
    }
}

// copy pre-split weight (128x64 uint32 pairs) into padded smem rows; 512 threads
__device__ __forceinline__ void load_Wbf(const uint32_t* __restrict__ Wh,
                                         const uint32_t* __restrict__ Wl,
                                         char* wHiB, char* wLoB, int tid)
{
    const uint2* wh = (const uint2*)Wh;
    const uint2* wl = (const uint2*)Wl;
    #pragma unroll
    for (int i = tid; i < 4096; i += NTH) {
        int n = i >> 5, p = i & 31;
        *(uint2*)(wHiB + n*ROWPAD + p*8) = wh[i];
        *(uint2*)(wLoB + n*ROWPAD + p*8) = wl[i];
    }
}

// per-thread ldmatrix addresses (16-warp layout: mb = wid&3, nb = wid>>2)
__device__ __forceinline__ uint32_t a_off(int mb, int l) {
    return (uint32_t)(mb*32*ROWPAD + (l & 15)*ROWPAD + ((l >> 4)*8)*2);
}
__device__ __forceinline__ uint32_t b_off(int nb, int l) {
    return (uint32_t)(nb*32*ROWPAD + ((l & 7) + ((l >> 4) << 3))*ROWPAD
                      + (((l >> 3) & 1)*8)*2);
}

// =======================================================================
// setup: bf16 hi/lo split of all weights ([out][in] layout kept)
// =======================================================================
__device__ __forceinline__ void splitw(float w0, float w1, uint32_t* H, uint32_t* L, int idx) {
    uint32_t hi = packbf(w0, w1);
    uint32_t lo = packbf(w0 - bflo(hi), w1 - bfhi(hi));
    H[idx] = hi; L[idx] = lo;
}

__global__ void k_prep(const float* __restrict__ offW1, const float* __restrict__ eW1,
                       const float* __restrict__ eW2,  const float* __restrict__ uW1,
                       const float* __restrict__ uW2)
{
    int tid = blockIdx.x*blockDim.x + threadIdx.x;
    if (tid >= 128*64) return;
    int p = tid & 63, n = tid >> 6;
    splitw(offW1[n*128 + 2*p], offW1[n*128 + 2*p + 1], g_oW1h, g_oW1l, tid);
    #pragma unroll
    for (int t = 0; t < TT; t++) {
        splitw(eW1[t*128*131 + n*131 + 3 + 2*p], eW1[t*128*131 + n*131 + 3 + 2*p + 1],
               g_eW1h, g_eW1l, t*8192 + tid);
        splitw(eW2[t*16384 + n*128 + 2*p], eW2[t*16384 + n*128 + 2*p + 1],
               g_eW2h, g_eW2l, t*8192 + tid);
        splitw(uW2[t*16384 + n*128 + 2*p], uW2[t*16384 + n*128 + 2*p + 1],
               g_uW2h, g_uW2l, t*8192 + tid);
        #pragma unroll
        for (int kb = 0; kb < 2; kb++)
            splitw(uW1[t*32768 + n*256 + kb*128 + 2*p], uW1[t*32768 + n*256 + kb*128 + 2*p + 1],
                   g_uW1h, g_uW1l, t*16384 + kb*8192 + tid);
    }
}

// =======================================================================
// Kernel A: offset MLP -> center -> bq AND GP.  Tile = 128 nodes, 512 thr.
// =======================================================================
#define AO_AH  0
#define AO_AL  34816
#define AO_W1H 69632
#define AO_W1L 104448
#define AO_WEH 139264
#define AO_WEL 174080
#define AO_F   208896
#define SMEM_KA (208896 + 3344*4)

__global__ __launch_bounds__(NTH, 1)
void kA(const float* __restrict__ xyz, const float* __restrict__ feat0, int first,
        const float* __restrict__ offb1, const float* __restrict__ offW2,
        const float* __restrict__ offb2,
        const float* __restrict__ eW1, const float* __restrict__ eb1, int t)
{
    extern __shared__ char smc[];
    const uint32_t sb = smem_u32(smc);
    float* sF     = (float*)(smc + AO_F);
    float* sXyz   = sF;           // 384
    float* sCen   = sF + 384;     // 384
    float* sPd    = sF + 768;     // 1536 (4 nb groups x 384)
    float* sW1x   = sF + 2304;    // 384
    float* sOffW2 = sF + 2688;    // 384
    float* sB1    = sF + 3072;    // 128
    float* sEB1   = sF + 3200;    // 128
    float* sB2    = sF + 3328;    // 16

    const int tid = threadIdx.x, wid = tid >> 5, l = tid & 31;
    const int mb = wid & 3, nb = wid >> 2;
    const float* fs = first ? feat0 : g_feat;

    load_Wbf(g_oW1h, g_oW1l, smc + AO_W1H, smc + AO_W1L, tid);
    load_Wbf(g_eW1h + t*8192, g_eW1l + t*8192, smc + AO_WEH, smc + AO_WEL, tid);
    for (int i = tid; i < 384; i += NTH) {
        int d = i >> 7, j = i & 127;
        sW1x[i] = eW1[j*131 + d];
        sOffW2[i] = offW2[i];
    }
    if (tid < 128) { sB1[tid] = offb1[tid]; sEB1[tid] = eb1[tid]; }
    if (tid < 3) sB2[tid] = offb2[tid];

    const uint32_t aHi = sb + AO_AH + a_off(mb, l),  aLo = sb + AO_AL + a_off(mb, l);
    const uint32_t w1H = sb + AO_W1H + b_off(nb, l), w1L = sb + AO_W1L + b_off(nb, l);
    const uint32_t weH = sb + AO_WEH + b_off(nb, l), weL = sb + AO_WEL + b_off(nb, l);
    __syncthreads();

    for (int tile = blockIdx.x; tile < BN/128; tile += gridDim.x) {
        const int n0 = tile * 128;
        asm_rows512(fs + (size_t)n0*128, smc + AO_AH, smc + AO_AL, tid);
        for (int i = tid; i < 384; i += NTH) sXyz[i] = xyz[(size_t)n0*3 + i];
        __syncthreads();

        float acc[2][4][4];
        zacc4(acc);
        mma_block4(aHi, aLo, w1H, w1L, acc);

        // delta partials
        float pr[2][2][3];
        #pragma unroll
        for (int a = 0; a < 2; a++)
            #pragma unroll
            for (int b = 0; b < 2; b++)
                #pragma unroll
                for (int d = 0; d < 3; d++) pr[a][b][d] = 0.f;
        #pragma unroll
        for (int mt = 0; mt < 2; mt++)
            #pragma unroll
            for (int nt = 0; nt < 4; nt++) {
                int c = nb*32 + nt*8 + (l & 3)*2;
                float h00 = fmaxf(acc[mt][nt][0] + sB1[c],   0.f);
                float h01 = fmaxf(acc[mt][nt][1] + sB1[c+1], 0.f);
                float h10 = fmaxf(acc[mt][nt][2] + sB1[c],   0.f);
                float h11 = fmaxf(acc[mt][nt][3] + sB1[c+1], 0.f);
                #pragma unroll
                for (int d = 0; d < 3; d++) {
                    float wa = sOffW2[d*128 + c], wb = sOffW2[d*128 + c + 1];
                    pr[mt][0][d] += h00*wa + h01*wb;
                    pr[mt][1][d] += h10*wa + h11*wb;
                }
            }
        #pragma unroll
        for (int mt = 0; mt < 2; mt++)
            #pragma unroll
            for (int rh = 0; rh < 2; rh++)
                #pragma unroll
                for (int d = 0; d < 3; d++) {
                    float v = pr[mt][rh][d];
                    v += __shfl_xor_sync(0xffffffffu, v, 1);
                    v += __shfl_xor_sync(0xffffffffu, v, 2);
                    pr[mt][rh][d] = v;
                }
        if ((l & 3) == 0) {
            #pragma unroll
            for (int mt = 0; mt < 2; mt++) {
                int r0 = mb*32 + mt*16 + (l >> 2);
                #pragma unroll
                for (int d = 0; d < 3; d++) {
                    sPd[nb*384 + r0*3 + d]     = pr[mt][0][d];
                    sPd[nb*384 + (r0+8)*3 + d] = pr[mt][1][d];
                }
            }
        }
        __syncthreads();

        if (tid < 384) {
            int o = tid, d = o - 3*(o/3);
            sCen[o] = sPd[o] + sPd[384+o] + sPd[768+o] + sPd[1152+o] + sB2[d] + sXyz[o];
        }
        __syncthreads();

        // GP GEMM (A unchanged)
        zacc4(acc);
        mma_block4(aHi, aLo, weH, weL, acc);

        #pragma unroll
        for (int mt = 0; mt < 2; mt++) {
            #pragma unroll
            for (int rh = 0; rh < 2; rh++) {
                int r = mb*32 + mt*16 + (l >> 2) + rh*8;
                float x0 = sXyz[r*3], x1 = sXyz[r*3+1], x2 = sXyz[r*3+2];
                float c0 = sCen[r*3], c1 = sCen[r*3+1], c2 = sCen[r*3+2];
                #pragma unroll
                for (int nt = 0; nt < 4; nt++) {
                    int c = nb*32 + nt*8 + (l & 3)*2;
                    float aL = acc[mt][nt][rh*2], aH = acc[mt][nt][rh*2+1];
                    float w0a = sW1x[c],       w0b = sW1x[c+1];
                    float w1a = sW1x[128 + c], w1b = sW1x[128 + c + 1];
                    float w2a = sW1x[256 + c], w2b = sW1x[256 + c + 1];
                    *(float2*)(g_GP + (size_t)(n0+r)*128 + c) =
                        make_float2(aL + x0*w0a + x1*w1a + x2*w2a,
                                    aH + x0*w0b + x1*w1b + x2*w2b);
                    *(float2*)(g_bq + (size_t)(n0+r)*128 + c) =
                        make_float2(sEB1[c]   - (c0*w0a + c1*w1a + c2*w2a),
                                    sEB1[c+1] - (c0*w0b + c1*w1b + c2*w2b));
                }
            }
        }
        __syncthreads();
    }
}

// =======================================================================
// Kernel Bm: edge layer-2 + max over K.  Tile = 8 nodes, 512 threads.
// =======================================================================
#define BO_WHI 0
#define BO_WLO 34816
#define BO_AHI 69632
#define BO_ALO 104448
#define BO_B2  139264
#define SMEM_BM (139264 + 512)

__global__ __launch_bounds__(NTH, 1)
void kBm(const int* __restrict__ knn, const float* __restrict__ eb2, int t)
{
    extern __shared__ char smc[];
    const uint32_t sb = smem_u32(smc);
    float* sB2 = (float*)(smc + BO_B2);

    const int tid = threadIdx.x;
    const int wid = tid >> 5, l = tid & 31;
    const int mb = wid & 3, nb = wid >> 2;

    load_Wbf(g_eW2h + t*8192, g_eW2l + t*8192, smc + BO_WHI, smc + BO_WLO, tid);
    if (tid < 128) sB2[tid] = eb2[tid];
    __syncthreads();

    const uint32_t aHi = sb + BO_AHI + a_off(mb, l), aLo = sb + BO_ALO + a_off(mb, l);
    const uint32_t bHi = sb + BO_WHI + b_off(nb, l), bLo = sb + BO_WLO + b_off(nb, l);

    const int r = tid & 127, q4 = tid >> 7;
    const int m = r >> 4;

    for (int tile = blockIdx.x; tile < BN/8; tile += gridDim.x) {
        const int n0 = tile * 8;

        // assemble A = relu(GP[gather] + bq), bf16 hi/lo
        {
            int gid = ((n0 >> 13) << 13) + knn[(size_t)n0*KK + r];
            const float4* src = (const float4*)(g_GP + (size_t)gid*128 + q4*32);
            const float4* bqv = (const float4*)(g_bq + (size_t)(n0 + m)*128 + q4*32);
            char* pH = smc + BO_AHI + r*ROWPAD + q4*64;
            char* pL = smc + BO_ALO + r*ROWPAD + q4*64;
            #pragma unroll
            for (int q = 0; q < 8; q++) {
                float4 v = src[q], w = bqv[q];
                float h0 = fmaxf(v.x + w.x, 0.f), h1 = fmaxf(v.y + w.y, 0.f);
                float h2 = fmaxf(v.z + w.z, 0.f), h3 = fmaxf(v.w + w.w, 0.f);
                uint32_t hA = packbf(h0, h1), hB = packbf(h2, h3);
                uint32_t lA = packbf(h0 - bflo(hA), h1 - bfhi(hA));
                uint32_t lB = packbf(h2 - bflo(hB), h3 - bfhi(hB));
                *(uint2*)(pH + q*8) = make_uint2(hA, hB);
                *(uint2*)(pL + q*8) = make_uint2(lA, lB);
            }
        }
        __syncthreads();

        float acc[2][4][4];
        zacc4(acc);
        mma_block4(aHi, aLo, bHi, bLo, acc);

        // max over K (16 rows per m16-tile = one node) + bias
        #pragma unroll
        for (int mt = 0; mt < 2; mt++) {
            int gn = n0 + mb*2 + mt;
            #pragma unroll
            for (int nt = 0; nt < 4; nt++) {
                float v0 = fmaxf(acc[mt][nt][0], acc[mt][nt][2]);
                float v1 = fmaxf(acc[mt][nt][1], acc[mt][nt][3]);
                #pragma unroll
                for (int o = 4; o <= 16; o <<= 1) {
                    v0 = fmaxf(v0, __shfl_xor_sync(0xffffffffu, v0, o));
                    v1 = fmaxf(v1, __shfl_xor_sync(0xffffffffu, v1, o));
                }
                if (l < 4) {
                    int col = nb*32 + nt*8 + l*2;
                    *(float2*)(g_agg + (size_t)gn*128 + col) =
                        make_float2(v0 + sB2[col], v1 + sB2[col+1]);
                }
            }
        }
        __syncthreads();
    }
}

// =======================================================================
// Kernel C (fused C1+C2): update MLP + residual.  Tile = 128 nodes, 512 thr.
// h kept in smem (bf16 split straight from accumulators).
// Weight buffer B0 rotates: uW1-chunk0 -> uW2 (reloaded per tile, L2-resident).
// =======================================================================
#define CO_AH  0
#define CO_AL  34816
#define CO_B0H 69632
#define CO_B0L 104448
#define CO_B1H 139264
#define CO_B1L 174080
#define CO_BIA 208896
#define SMEM_KC (208896 + 1024)

__global__ __launch_bounds__(NTH, 1)
void kC(const float* __restrict__ feat0, int first,
        const float* __restrict__ ub1, const float* __restrict__ ub2,
        float* __restrict__ outp, int write_out, int t)
{
    extern __shared__ char smc[];
    const uint32_t sb = smem_u32(smc);
    float* sB1 = (float*)(smc + CO_BIA);
    float* sB2 = (float*)(smc + CO_BIA + 512);

    const int tid = threadIdx.x, wid = tid >> 5, l = tid & 31;
    const int mb = wid & 3, nb = wid >> 2;
    const float* fs = first ? feat0 : g_feat;

    load_Wbf(g_uW1h + t*16384 + 8192, g_uW1l + t*16384 + 8192,
             smc + CO_B1H, smc + CO_B1L, tid);   // chunk1 (feat cols), persistent
    if (tid < 128) { sB1[tid] = ub1[tid]; sB2[tid] = ub2[tid]; }

    const uint32_t aHi = sb + CO_AH + a_off(mb, l),  aLo = sb + CO_AL + a_off(mb, l);
    const uint32_t b0H = sb + CO_B0H + b_off(nb, l), b0L = sb + CO_B0L + b_off(nb, l);
    const uint32_t b1H = sb + CO_B1H + b_off(nb, l), b1L = sb + CO_B1L + b_off(nb, l);

    for (int tile = blockIdx.x; tile < BN/128; tile += gridDim.x) {
        const int n0 = tile * 128;

        // chunk0: A = agg, W = uW1 chunk0 (loaded into rotating B0)
        load_Wbf(g_uW1h + t*16384, g_uW1l + t*16384, smc + CO_B0H, smc + CO_B0L, tid);
        asm_rows512(g_agg + (size_t)n0*128, smc + CO_AH, smc + CO_AL, tid);
        __syncthreads();

        float acc[2][4][4];
        zacc4(acc);
        mma_block4(aHi, aLo, b0H, b0L, acc);
        __syncthreads();   // done reading A and B0

        // chunk1: A = feat, W = uW1 chunk1; meanwhile rotate B0 <- uW2
        asm_rows512(fs + (size_t)n0*128, smc + CO_AH, smc + CO_AL, tid);
        load_Wbf(g_uW2h + t*8192, g_uW2l + t*8192, smc + CO_B0H, smc + CO_B0L, tid);
        __syncthreads();
        mma_block4(aHi, aLo, b1H, b1L, acc);
        __syncthreads();   // done reading A (h overwrite next)

        // h = relu(acc + b1) -> straight into A buffer as bf16 hi/lo
        #pragma unroll
        for (int mt = 0; mt < 2; mt++) {
            #pragma unroll
            for (int rh = 0; rh < 2; rh++) {
                int r = mb*32 + mt*16 + (l >> 2) + rh*8;
                #pragma unroll
                for (int nt = 0; nt < 4; nt++) {
                    int c = nb*32 + nt*8 + (l & 3)*2;
                    float h0 = fmaxf(acc[mt][nt][rh*2]   + sB1[c],   0.f);
                    float h1 = fmaxf(acc[mt][nt][rh*2+1] + sB1[c+1], 0.f);
                    uint32_t hi = packbf(h0, h1);
                    uint32_t lo = packbf(h0 - bflo(hi), h1 - bfhi(hi));
                    *(uint32_t*)(smc + CO_AH + r*ROWPAD + c*2) = hi;
                    *(uint32_t*)(smc + CO_AL + r*ROWPAD + c*2) = lo;
                }
            }
        }
        __syncthreads();

        // layer 2: A = h, W = uW2 (in B0)
        zacc4(acc);
        mma_block4(aHi, aLo, b0H, b0L, acc);

        #pragma unroll
        for (int mt = 0; mt < 2; mt++) {
            #pragma unroll
            for (int rh = 0; rh < 2; rh++) {
                int r = mb*32 + mt*16 + (l >> 2) + rh*8;
                #pragma unroll
                for (int nt = 0; nt < 4; nt++) {
                    int c = nb*32 + nt*8 + (l & 3)*2;
                    float2 f = *(const float2*)(fs + (size_t)(n0+r)*128 + c);
                    float2 v = make_float2(f.x + acc[mt][nt][rh*2]   + sB2[c],
                                           f.y + acc[mt][nt][rh*2+1] + sB2[c+1]);
                    *(float2*)(g_feat + (size_t)(n0+r)*128 + c) = v;
                    if (write_out) *(float2*)(outp + (size_t)(n0+r)*128 + c) = v;
                }
            }
        }
        __syncthreads();   // protect A/B0 for next tile
    }
}

// =======================================================================
// launch
// =======================================================================
extern "C" void kernel_launch(void* const* d_in, const int* in_sizes, int n_in,
                              void* d_out, int out_size) {
    const float* xyz   = (const float*)d_in[0];
    const float* feat0 = (const float*)d_in[1];
    const int*   knn   = (const int*)d_in[2];
    const float* offW1 = (const float*)d_in[3];
    const float* offb1 = (const float*)d_in[4];
    const float* offW2 = (const float*)d_in[5];
    const float* offb2 = (const float*)d_in[6];
    const float* eW1   = (const float*)d_in[7];
    const float* eb1   = (const float*)d_in[8];
    const float* eW2   = (const float*)d_in[9];
    const float* eb2   = (const float*)d_in[10];
    const float* uW1   = (const float*)d_in[11];
    const float* ub1   = (const float*)d_in[12];
    const float* uW2   = (const float*)d_in[13];
    const float* ub2   = (const float*)d_in[14];
    float* outp = (float*)d_out;

    cudaFuncSetAttribute(kA,  cudaFuncAttributeMaxDynamicSharedMemorySize, SMEM_KA);
    cudaFuncSetAttribute(kBm, cudaFuncAttributeMaxDynamicSharedMemorySize, SMEM_BM);
    cudaFuncSetAttribute(kC,  cudaFuncAttributeMaxDynamicSharedMemorySize, SMEM_KC);

    k_prep<<<32, 256>>>(offW1, eW1, eW2, uW1, uW2);

    for (int t = 0; t < TT; t++) {
        int first = (t == 0) ? 1 : 0;
        kA<<<NSM, NTH, SMEM_KA>>>(xyz, feat0, first, offb1, offW2, offb2,
                                  eW1 + (size_t)t*CC*(3+CC), eb1 + (size_t)t*CC, t);
        kBm<<<NSM, NTH, SMEM_BM>>>(knn, eb2 + (size_t)t*CC, t);
        kC<<<NSM, NTH, SMEM_KC>>>(feat0, first, ub1 + (size_t)t*CC, ub2 + (size_t)t*CC,
                                  outp, (t == TT-1) ? 1 : 0, t);
    }
}